// round 8
// baseline (speedup 1.0000x reference)
#include <cuda_runtime.h>
#include <cuda_bf16.h>
#include <math.h>

// BlockGCN fused, round 8: t-pair threads (shared weight LDCU + bcol hoists),
// k-fused passes. out = relu(BN(sum_k conv_k(einsum(x,BnA_k))) + x)

#define NK 3
#define NH 8
#define NV 23
#define NVP 24
#define BSTRIDE 36
#define CG 16
#define NT 256
#define NN 32
#define NC 128
#define TB 16            // timesteps per block (8 t-pairs)
#define THREADS 184      // 8 t-pairs x 23 w

typedef unsigned long long ull;

__device__ __forceinline__ ull fma2(ull a, ull b, ull c) {
    ull d;
    asm("fma.rn.f32x2 %0, %1, %2, %3;" : "=l"(d) : "l"(a), "l"(b), "l"(c));
    return d;
}
__device__ __forceinline__ ull add2(ull a, ull b) {
    ull d;
    asm("add.rn.f32x2 %0, %1, %2;" : "=l"(d) : "l"(a), "l"(b));
    return d;
}
__device__ __forceinline__ ull pack2(float lo, float hi) {
    ull d;
    asm("mov.b64 %0, {%1, %2};" : "=l"(d) : "f"(lo), "f"(hi));
    return d;
}
__device__ __forceinline__ void unpack2(ull v, float& lo, float& hi) {
    asm("mov.b64 {%0, %1}, %2;" : "=f"(lo), "=f"(hi) : "l"(v));
}
__device__ __forceinline__ float hsum2(ull v) {
    float lo, hi;
    unpack2(v, lo, hi);
    return lo + hi;
}

// Precompute outputs (device globals; no allocation).
__device__ float g_bna[NK][NH][NV][NVP];   // [k][h][w][v], v padded with 0
__device__ ull   g_ws2[NK * NH * CG * 8];  // pack(ws[o0],ws[o1]) o-pairs, BN folded
__device__ ull   g_bias2[NH * 8];          // folded bias o-pairs

// Constant mirrors (async D2D copy; capture-legal, proven R4-R7).
__constant__ ull c_ws2[NK * NH * CG * 8];  // 24 KB
__constant__ ull c_bias2[NH * 8];

__global__ void precompute_kernel(const float* __restrict__ emb,
                                  const float* __restrict__ A,
                                  const float* __restrict__ conv_w,
                                  const float* __restrict__ conv_b,
                                  const float* __restrict__ gamma,
                                  const float* __restrict__ beta,
                                  const float* __restrict__ mean,
                                  const float* __restrict__ var,
                                  const int*   __restrict__ hop,
                                  int n_hop)
{
    int b = blockIdx.x;
    int tid = threadIdx.x;
    if (b < NK * NH) {
        int k = b / NH, h = b % NH;
        int w = tid;
        if (w < NV) {
            float Bc[NV], Ac[NV];
            float sB = 0.f, sA = 0.f;
            #pragma unroll
            for (int v = 0; v < NV; v++) {
                float bb = emb[(k * NH + h) * n_hop + hop[v * NV + w]];
                float aa = A[((k * NH + h) * NV + v) * NV + w];
                Bc[v] = bb; Ac[v] = aa;
                sB += bb * bb; sA += aa * aa;
            }
            float iB = 1.f / (sqrtf(sB) + 1e-4f);
            float iA = 1.f / (sqrtf(sA) + 1e-4f);
            #pragma unroll
            for (int v = 0; v < NV; v++)
                g_bna[k][h][w][v] = Bc[v] * iB + Ac[v] * iA;
            g_bna[k][h][w][NV] = 0.f;
        }
    } else {
        for (int idx = tid; idx < NK * NH * CG * 8; idx += blockDim.x) {
            int q = idx % 8;
            int c = (idx / 8) % CG;
            int h = (idx / (8 * CG)) % NH;
            int k = idx / (8 * CG * NH);
            int och0 = h * CG + 2 * q, och1 = och0 + 1;
            float inv0 = gamma[och0] * rsqrtf(var[och0] + 1e-5f);
            float inv1 = gamma[och1] * rsqrtf(var[och1] + 1e-5f);
            float w0 = conv_w[(k * NC + och0) * CG + c] * inv0;
            float w1 = conv_w[(k * NC + och1) * CG + c] * inv1;
            g_ws2[idx] = pack2(w0, w1);
        }
        for (int idx = tid; idx < NH * 8; idx += blockDim.x) {
            int q = idx % 8, h = idx / 8;
            float bv[2];
            #pragma unroll
            for (int j = 0; j < 2; j++) {
                int och = h * CG + 2 * q + j;
                float inv = gamma[och] * rsqrtf(var[och] + 1e-5f);
                float sb = conv_b[och] + conv_b[NC + och] + conv_b[2 * NC + och];
                bv[j] = sb * inv + beta[och] - mean[och] * inv;
            }
            g_bias2[idx] = pack2(bv[0], bv[1]);
        }
    }
}

__global__ __launch_bounds__(THREADS, 3)
void blockgcn_main_kernel(const float* __restrict__ x, float* __restrict__ out)
{
    __shared__ __align__(16) float xs[CG][TB][NVP];       // 24576 B
    __shared__ __align__(16) float bnas[NK][NV][BSTRIDE]; //  9936 B

    const int tile = blockIdx.x;   // 0..15
    const int n    = blockIdx.y;   // 0..31
    const int h    = blockIdx.z;   // 0..7
    const int t0b  = tile * TB;
    const int tid  = threadIdx.x;

    // ---- stage x tile (float4 LDG, scalar STS scatter) ----
    const float* xbase = x + ((size_t)(n * NC + h * CG)) * (NT * NV) + (size_t)t0b * NV;
    for (int idx = tid; idx < CG * TB * NV / 4; idx += THREADS) {  // 1472 float4
        int c  = idx / (TB * NV / 4);
        int r4 = idx % (TB * NV / 4);
        float4 f = ((const float4*)(xbase + (size_t)c * (NT * NV)))[r4];
        int lin = r4 * 4;
        xs[c][lin / NV][lin % NV] = f.x;  lin++;
        xs[c][lin / NV][lin % NV] = f.y;  lin++;
        xs[c][lin / NV][lin % NV] = f.z;  lin++;
        xs[c][lin / NV][lin % NV] = f.w;
    }
    for (int idx = tid; idx < CG * TB; idx += THREADS)
        xs[idx / TB][idx % TB][NV] = 0.f;

    // ---- stage BnA ([k][w][v] rows, stride 36 floats, this h) ----
    for (int idx = tid; idx < NK * NV * NVP; idx += THREADS) {
        int k = idx / (NV * NVP), rem = idx % (NV * NVP);
        bnas[k][rem / NVP][rem % NVP] = (&g_bna[k][h][0][0])[rem];
    }
    __syncthreads();

    {
        const int tp = tid / NV;        // t-pair index 0..7
        const int w  = tid % NV;
        const int t0 = 2 * tp, t1 = 2 * tp + 1;

        // init: folded bias + residual, o-pairs, per timestep
        ull accA[8], accB[8];
        #pragma unroll
        for (int q = 0; q < 8; q++) {
            ull bq = c_bias2[h * 8 + q];
            accA[q] = add2(bq, pack2(xs[2 * q][t0][w], xs[2 * q + 1][t0][w]));
            accB[q] = add2(bq, pack2(xs[2 * q][t1][w], xs[2 * q + 1][t1][w]));
        }

        // ===== Pass A: k=0 and k=1 fused =====
        {
            ull b0[12], b1[12];
            {
                const ulonglong2* bp0 = (const ulonglong2*)&bnas[0][w][0];
                const ulonglong2* bp1 = (const ulonglong2*)&bnas[1][w][0];
                #pragma unroll
                for (int q = 0; q < 6; q++) {
                    ulonglong2 u0 = bp0[q], u1 = bp1[q];
                    b0[2 * q] = u0.x; b0[2 * q + 1] = u0.y;
                    b1[2 * q] = u1.x; b1[2 * q + 1] = u1.y;
                }
            }
            #pragma unroll 1
            for (int c = 0; c < CG; c++) {
                const ulonglong2* xp0 = (const ulonglong2*)&xs[c][t0][0];
                const ulonglong2* xp1 = (const ulonglong2*)&xs[c][t1][0];
                ull s00 = 0ull, s10 = 0ull, s01 = 0ull, s11 = 0ull; // s[k][t]
                #pragma unroll
                for (int q = 0; q < 6; q++) {
                    ulonglong2 u0 = xp0[q];
                    ulonglong2 u1 = xp1[q];
                    s00 = fma2(u0.x, b0[2 * q],     s00);
                    s00 = fma2(u0.y, b0[2 * q + 1], s00);
                    s10 = fma2(u0.x, b1[2 * q],     s10);
                    s10 = fma2(u0.y, b1[2 * q + 1], s10);
                    s01 = fma2(u1.x, b0[2 * q],     s01);
                    s01 = fma2(u1.y, b0[2 * q + 1], s01);
                    s11 = fma2(u1.x, b1[2 * q],     s11);
                    s11 = fma2(u1.y, b1[2 * q + 1], s11);
                }
                float f00 = hsum2(s00), f10 = hsum2(s10);
                float f01 = hsum2(s01), f11 = hsum2(s11);
                ull sp00 = pack2(f00, f00), sp10 = pack2(f10, f10);
                ull sp01 = pack2(f01, f01), sp11 = pack2(f11, f11);
                const ull* wp0 = &c_ws2[((0 * NH + h) * CG + c) * 8];
                const ull* wp1 = &c_ws2[((1 * NH + h) * CG + c) * 8];
                #pragma unroll
                for (int q = 0; q < 8; q++) {
                    ull w0 = wp0[q], w1 = wp1[q];   // LDCU shared by both t
                    accA[q] = fma2(sp10, w1, fma2(sp00, w0, accA[q]));
                    accB[q] = fma2(sp11, w1, fma2(sp01, w0, accB[q]));
                }
            }
        }

        // ===== Pass B: k=2 =====
        {
            ull b2[12];
            {
                const ulonglong2* bp = (const ulonglong2*)&bnas[2][w][0];
                #pragma unroll
                for (int q = 0; q < 6; q++) {
                    ulonglong2 u = bp[q];
                    b2[2 * q] = u.x; b2[2 * q + 1] = u.y;
                }
            }
            #pragma unroll 1
            for (int c = 0; c < CG; c++) {
                const ulonglong2* xp0 = (const ulonglong2*)&xs[c][t0][0];
                const ulonglong2* xp1 = (const ulonglong2*)&xs[c][t1][0];
                ull s0 = 0ull, s1 = 0ull;
                #pragma unroll
                for (int q = 0; q < 6; q++) {
                    ulonglong2 u0 = xp0[q];
                    ulonglong2 u1 = xp1[q];
                    s0 = fma2(u0.x, b2[2 * q],     s0);
                    s0 = fma2(u0.y, b2[2 * q + 1], s0);
                    s1 = fma2(u1.x, b2[2 * q],     s1);
                    s1 = fma2(u1.y, b2[2 * q + 1], s1);
                }
                float f0 = hsum2(s0), f1 = hsum2(s1);
                ull sp0 = pack2(f0, f0), sp1 = pack2(f1, f1);
                const ull* wp = &c_ws2[((2 * NH + h) * CG + c) * 8];
                #pragma unroll
                for (int q = 0; q < 8; q++) {
                    ull wq = wp[q];
                    accA[q] = fma2(sp0, wq, accA[q]);
                    accB[q] = fma2(sp1, wq, accB[q]);
                }
            }
        }

        // epilogue: relu + store both timesteps
        float* ob = out + ((size_t)(n * NC + h * CG)) * (NT * NV)
                        + (size_t)(t0b + t0) * NV + w;
        #pragma unroll
        for (int q = 0; q < 8; q++) {
            float a0, a1, b0f, b1f;
            unpack2(accA[q], a0, a1);
            unpack2(accB[q], b0f, b1f);
            ob[(size_t)(2 * q)     * (NT * NV)]      = fmaxf(a0, 0.f);
            ob[(size_t)(2 * q + 1) * (NT * NV)]      = fmaxf(a1, 0.f);
            ob[(size_t)(2 * q)     * (NT * NV) + NV] = fmaxf(b0f, 0.f);
            ob[(size_t)(2 * q + 1) * (NT * NV) + NV] = fmaxf(b1f, 0.f);
        }
    }
}

extern "C" void kernel_launch(void* const* d_in, const int* in_sizes, int n_in,
                              void* d_out, int out_size)
{
    const float* x      = (const float*)d_in[0];
    const float* emb    = (const float*)d_in[1];
    const float* A      = (const float*)d_in[2];
    const float* conv_w = (const float*)d_in[3];
    const float* conv_b = (const float*)d_in[4];
    const float* gamma  = (const float*)d_in[5];
    const float* beta   = (const float*)d_in[6];
    const float* mean   = (const float*)d_in[7];
    const float* var    = (const float*)d_in[8];
    const int*   hop    = (const int*)d_in[9];

    int n_hop = in_sizes[1] / (NK * NH);

    precompute_kernel<<<NK * NH + 1, 256>>>(emb, A, conv_w, conv_b,
                                            gamma, beta, mean, var, hop, n_hop);

    void* ws2_src = nullptr;
    void* bias2_src = nullptr;
    cudaGetSymbolAddress(&ws2_src, g_ws2);
    cudaGetSymbolAddress(&bias2_src, g_bias2);
    cudaMemcpyToSymbolAsync(c_ws2, ws2_src, sizeof(ull) * NK * NH * CG * 8, 0,
                            cudaMemcpyDeviceToDevice, 0);
    cudaMemcpyToSymbolAsync(c_bias2, bias2_src, sizeof(ull) * NH * 8, 0,
                            cudaMemcpyDeviceToDevice, 0);

    dim3 grid(NT / TB, NN, NH);
    blockgcn_main_kernel<<<grid, THREADS>>>(x, (float*)d_out);
}

// round 9
// speedup vs baseline: 1.1613x; 1.1613x over previous
#include <cuda_runtime.h>
#include <cuda_bf16.h>
#include <math.h>

// BlockGCN fused, round 9: FULL k-fusion (x read once per c), 184-thr blocks,
// 3 blocks/SM. out = relu(BN(sum_k conv_k(einsum(x,BnA_k))) + x)

#define NK 3
#define NH 8
#define NV 23
#define NVP 24
#define BSTRIDE 36
#define CG 16
#define NT 256
#define NN 32
#define NC 128
#define TB 8
#define THREADS 184      // 8 t x 23 w

typedef unsigned long long ull;

__device__ __forceinline__ ull fma2(ull a, ull b, ull c) {
    ull d;
    asm("fma.rn.f32x2 %0, %1, %2, %3;" : "=l"(d) : "l"(a), "l"(b), "l"(c));
    return d;
}
__device__ __forceinline__ ull add2(ull a, ull b) {
    ull d;
    asm("add.rn.f32x2 %0, %1, %2;" : "=l"(d) : "l"(a), "l"(b));
    return d;
}
__device__ __forceinline__ ull pack2(float lo, float hi) {
    ull d;
    asm("mov.b64 %0, {%1, %2};" : "=l"(d) : "f"(lo), "f"(hi));
    return d;
}
__device__ __forceinline__ void unpack2(ull v, float& lo, float& hi) {
    asm("mov.b64 {%0, %1}, %2;" : "=f"(lo), "=f"(hi) : "l"(v));
}
__device__ __forceinline__ float hsum2(ull v) {
    float lo, hi;
    unpack2(v, lo, hi);
    return lo + hi;
}

// Precompute outputs (device globals; no allocation).
__device__ float g_bna[NK][NH][NV][NVP];   // [k][h][w][v], v padded with 0
__device__ ull   g_ws2[NK * NH * CG * 8];  // pack(ws[o0],ws[o1]) o-pairs, BN folded
__device__ ull   g_bias2[NH * 8];          // folded bias o-pairs

// Constant mirrors (async D2D copy; capture-legal, proven R4-R8).
__constant__ ull c_ws2[NK * NH * CG * 8];  // 24 KB
__constant__ ull c_bias2[NH * 8];

__global__ void precompute_kernel(const float* __restrict__ emb,
                                  const float* __restrict__ A,
                                  const float* __restrict__ conv_w,
                                  const float* __restrict__ conv_b,
                                  const float* __restrict__ gamma,
                                  const float* __restrict__ beta,
                                  const float* __restrict__ mean,
                                  const float* __restrict__ var,
                                  const int*   __restrict__ hop,
                                  int n_hop)
{
    int b = blockIdx.x;
    int tid = threadIdx.x;
    if (b < NK * NH) {
        int k = b / NH, h = b % NH;
        int w = tid;
        if (w < NV) {
            float Bc[NV], Ac[NV];
            float sB = 0.f, sA = 0.f;
            #pragma unroll
            for (int v = 0; v < NV; v++) {
                float bb = emb[(k * NH + h) * n_hop + hop[v * NV + w]];
                float aa = A[((k * NH + h) * NV + v) * NV + w];
                Bc[v] = bb; Ac[v] = aa;
                sB += bb * bb; sA += aa * aa;
            }
            float iB = 1.f / (sqrtf(sB) + 1e-4f);
            float iA = 1.f / (sqrtf(sA) + 1e-4f);
            #pragma unroll
            for (int v = 0; v < NV; v++)
                g_bna[k][h][w][v] = Bc[v] * iB + Ac[v] * iA;
            g_bna[k][h][w][NV] = 0.f;
        }
    } else {
        for (int idx = tid; idx < NK * NH * CG * 8; idx += blockDim.x) {
            int q = idx % 8;
            int c = (idx / 8) % CG;
            int h = (idx / (8 * CG)) % NH;
            int k = idx / (8 * CG * NH);
            int och0 = h * CG + 2 * q, och1 = och0 + 1;
            float inv0 = gamma[och0] * rsqrtf(var[och0] + 1e-5f);
            float inv1 = gamma[och1] * rsqrtf(var[och1] + 1e-5f);
            float w0 = conv_w[(k * NC + och0) * CG + c] * inv0;
            float w1 = conv_w[(k * NC + och1) * CG + c] * inv1;
            g_ws2[idx] = pack2(w0, w1);
        }
        for (int idx = tid; idx < NH * 8; idx += blockDim.x) {
            int q = idx % 8, h = idx / 8;
            float bv[2];
            #pragma unroll
            for (int j = 0; j < 2; j++) {
                int och = h * CG + 2 * q + j;
                float inv = gamma[och] * rsqrtf(var[och] + 1e-5f);
                float sb = conv_b[och] + conv_b[NC + och] + conv_b[2 * NC + och];
                bv[j] = sb * inv + beta[och] - mean[och] * inv;
            }
            g_bias2[idx] = pack2(bv[0], bv[1]);
        }
    }
}

__global__ __launch_bounds__(THREADS, 3)
void blockgcn_main_kernel(const float* __restrict__ x, float* __restrict__ out)
{
    __shared__ __align__(16) float xs[CG][TB][NVP];       // 12288 B
    __shared__ __align__(16) float bnas[NK][NV][BSTRIDE]; //  9936 B

    const int tile = blockIdx.x;   // 0..31
    const int n    = blockIdx.y;   // 0..31
    const int h    = blockIdx.z;   // 0..7
    const int t0   = tile * TB;
    const int tid  = threadIdx.x;

    // ---- stage x tile (float4 LDG, scalar STS scatter) ----
    const float* xbase = x + ((size_t)(n * NC + h * CG)) * (NT * NV) + (size_t)t0 * NV;
    for (int idx = tid; idx < CG * TB * NV / 4; idx += THREADS) {  // 736 float4
        int c  = idx / (TB * NV / 4);
        int r4 = idx % (TB * NV / 4);
        float4 f = ((const float4*)(xbase + (size_t)c * (NT * NV)))[r4];
        int lin = r4 * 4;
        xs[c][lin / NV][lin % NV] = f.x;  lin++;
        xs[c][lin / NV][lin % NV] = f.y;  lin++;
        xs[c][lin / NV][lin % NV] = f.z;  lin++;
        xs[c][lin / NV][lin % NV] = f.w;
    }
    for (int idx = tid; idx < CG * TB; idx += THREADS)
        xs[idx / TB][idx % TB][NV] = 0.f;

    // ---- stage BnA ([k][w][v] rows, stride 36 floats, this h) ----
    for (int idx = tid; idx < NK * NV * NVP; idx += THREADS) {
        int k = idx / (NV * NVP), rem = idx % (NV * NVP);
        bnas[k][rem / NVP][rem % NVP] = (&g_bna[k][h][0][0])[rem];
    }
    __syncthreads();

    {
        const int t = tid / NV;
        const int w = tid % NV;

        // init: folded bias + residual, packed over o-pairs
        ull acc2[8];
        #pragma unroll
        for (int q = 0; q < 8; q++)
            acc2[q] = add2(c_bias2[h * 8 + q],
                           pack2(xs[2 * q][t][w], xs[2 * q + 1][t][w]));

        // hoist ALL 3 BnA columns for this w (72 regs, reused for all 16 c)
        ull b0[12], b1[12], b2[12];
        {
            const ulonglong2* bp0 = (const ulonglong2*)&bnas[0][w][0];
            const ulonglong2* bp1 = (const ulonglong2*)&bnas[1][w][0];
            const ulonglong2* bp2 = (const ulonglong2*)&bnas[2][w][0];
            #pragma unroll
            for (int q = 0; q < 6; q++) {
                ulonglong2 u0 = bp0[q], u1 = bp1[q], u2 = bp2[q];
                b0[2 * q] = u0.x; b0[2 * q + 1] = u0.y;
                b1[2 * q] = u1.x; b1[2 * q + 1] = u1.y;
                b2[2 * q] = u2.x; b2[2 * q + 1] = u2.y;
            }
        }

        // single pass over c: x row read ONCE, feeds all 3 k-dots
        #pragma unroll 2
        for (int c = 0; c < CG; c++) {
            const ulonglong2* xp = (const ulonglong2*)&xs[c][t][0];
            ull s0 = 0ull, s1 = 0ull, s2 = 0ull;
            #pragma unroll
            for (int q = 0; q < 6; q++) {
                ulonglong2 u = xp[q];          // consumed immediately
                s0 = fma2(u.x, b0[2 * q],     s0);
                s1 = fma2(u.x, b1[2 * q],     s1);
                s2 = fma2(u.x, b2[2 * q],     s2);
                s0 = fma2(u.y, b0[2 * q + 1], s0);
                s1 = fma2(u.y, b1[2 * q + 1], s1);
                s2 = fma2(u.y, b2[2 * q + 1], s2);
            }
            float f0 = hsum2(s0), f1 = hsum2(s1), f2 = hsum2(s2);
            ull sp0 = pack2(f0, f0);
            ull sp1 = pack2(f1, f1);
            ull sp2 = pack2(f2, f2);
            const ull* wp0 = &c_ws2[((0 * NH + h) * CG + c) * 8];
            const ull* wp1 = &c_ws2[((1 * NH + h) * CG + c) * 8];
            const ull* wp2 = &c_ws2[((2 * NH + h) * CG + c) * 8];
            #pragma unroll
            for (int q = 0; q < 8; q++)
                acc2[q] = fma2(sp2, wp2[q],
                          fma2(sp1, wp1[q],
                          fma2(sp0, wp0[q], acc2[q])));
        }

        // epilogue: relu + store
        float* ob = out + ((size_t)(n * NC + h * CG)) * (NT * NV)
                        + (size_t)(t0 + t) * NV + w;
        #pragma unroll
        for (int q = 0; q < 8; q++) {
            float a, b;
            unpack2(acc2[q], a, b);
            ob[(size_t)(2 * q)     * (NT * NV)] = fmaxf(a, 0.f);
            ob[(size_t)(2 * q + 1) * (NT * NV)] = fmaxf(b, 0.f);
        }
    }
}

extern "C" void kernel_launch(void* const* d_in, const int* in_sizes, int n_in,
                              void* d_out, int out_size)
{
    const float* x      = (const float*)d_in[0];
    const float* emb    = (const float*)d_in[1];
    const float* A      = (const float*)d_in[2];
    const float* conv_w = (const float*)d_in[3];
    const float* conv_b = (const float*)d_in[4];
    const float* gamma  = (const float*)d_in[5];
    const float* beta   = (const float*)d_in[6];
    const float* mean   = (const float*)d_in[7];
    const float* var    = (const float*)d_in[8];
    const int*   hop    = (const int*)d_in[9];

    int n_hop = in_sizes[1] / (NK * NH);

    precompute_kernel<<<NK * NH + 1, 256>>>(emb, A, conv_w, conv_b,
                                            gamma, beta, mean, var, hop, n_hop);

    void* ws2_src = nullptr;
    void* bias2_src = nullptr;
    cudaGetSymbolAddress(&ws2_src, g_ws2);
    cudaGetSymbolAddress(&bias2_src, g_bias2);
    cudaMemcpyToSymbolAsync(c_ws2, ws2_src, sizeof(ull) * NK * NH * CG * 8, 0,
                            cudaMemcpyDeviceToDevice, 0);
    cudaMemcpyToSymbolAsync(c_bias2, bias2_src, sizeof(ull) * NH * 8, 0,
                            cudaMemcpyDeviceToDevice, 0);

    dim3 grid(NT / TB, NN, NH);
    blockgcn_main_kernel<<<grid, THREADS>>>(x, (float*)d_out);
}

// round 10
// speedup vs baseline: 1.1649x; 1.0031x over previous
#include <cuda_runtime.h>
#include <cuda_bf16.h>
#include <math.h>

// BlockGCN fused, round 10: R9 + vectorized LDCU.128 weight stream + addr
// hygiene. out = relu(BN(sum_k conv_k(einsum(x,BnA_k))) + x)

#define NK 3
#define NH 8
#define NV 23
#define NVP 24
#define BSTRIDE 36
#define CG 16
#define NT 256
#define NN 32
#define NC 128
#define TB 8
#define THREADS 184      // 8 t x 23 w

typedef unsigned long long ull;

__device__ __forceinline__ ull fma2(ull a, ull b, ull c) {
    ull d;
    asm("fma.rn.f32x2 %0, %1, %2, %3;" : "=l"(d) : "l"(a), "l"(b), "l"(c));
    return d;
}
__device__ __forceinline__ ull add2(ull a, ull b) {
    ull d;
    asm("add.rn.f32x2 %0, %1, %2;" : "=l"(d) : "l"(a), "l"(b));
    return d;
}
__device__ __forceinline__ ull pack2(float lo, float hi) {
    ull d;
    asm("mov.b64 %0, {%1, %2};" : "=l"(d) : "f"(lo), "f"(hi));
    return d;
}
__device__ __forceinline__ void unpack2(ull v, float& lo, float& hi) {
    asm("mov.b64 {%0, %1}, %2;" : "=f"(lo), "=f"(hi) : "l"(v));
}
__device__ __forceinline__ float hsum2(ull v) {
    float lo, hi;
    unpack2(v, lo, hi);
    return lo + hi;
}

// Precompute outputs (device globals; no allocation).
__device__ float g_bna[NK][NH][NV][NVP];   // [k][h][w][v], v padded with 0
__device__ ull   g_ws2[NK * NH * CG * 8];  // pack(ws[o0],ws[o1]) o-pairs, BN folded
__device__ ull   g_bias2[NH * 8];          // folded bias o-pairs

// Constant mirrors (async D2D copy; capture-legal, proven R4-R9).
__constant__ __align__(16) ull c_ws2[NK * NH * CG * 8];  // 24 KB
__constant__ __align__(16) ull c_bias2[NH * 8];

__global__ void precompute_kernel(const float* __restrict__ emb,
                                  const float* __restrict__ A,
                                  const float* __restrict__ conv_w,
                                  const float* __restrict__ conv_b,
                                  const float* __restrict__ gamma,
                                  const float* __restrict__ beta,
                                  const float* __restrict__ mean,
                                  const float* __restrict__ var,
                                  const int*   __restrict__ hop,
                                  int n_hop)
{
    int b = blockIdx.x;
    int tid = threadIdx.x;
    if (b < NK * NH) {
        int k = b / NH, h = b % NH;
        int w = tid;
        if (w < NV) {
            float Bc[NV], Ac[NV];
            float sB = 0.f, sA = 0.f;
            #pragma unroll
            for (int v = 0; v < NV; v++) {
                float bb = emb[(k * NH + h) * n_hop + hop[v * NV + w]];
                float aa = A[((k * NH + h) * NV + v) * NV + w];
                Bc[v] = bb; Ac[v] = aa;
                sB += bb * bb; sA += aa * aa;
            }
            float iB = 1.f / (sqrtf(sB) + 1e-4f);
            float iA = 1.f / (sqrtf(sA) + 1e-4f);
            #pragma unroll
            for (int v = 0; v < NV; v++)
                g_bna[k][h][w][v] = Bc[v] * iB + Ac[v] * iA;
            g_bna[k][h][w][NV] = 0.f;
        }
    } else {
        for (int idx = tid; idx < NK * NH * CG * 8; idx += blockDim.x) {
            int q = idx % 8;
            int c = (idx / 8) % CG;
            int h = (idx / (8 * CG)) % NH;
            int k = idx / (8 * CG * NH);
            int och0 = h * CG + 2 * q, och1 = och0 + 1;
            float inv0 = gamma[och0] * rsqrtf(var[och0] + 1e-5f);
            float inv1 = gamma[och1] * rsqrtf(var[och1] + 1e-5f);
            float w0 = conv_w[(k * NC + och0) * CG + c] * inv0;
            float w1 = conv_w[(k * NC + och1) * CG + c] * inv1;
            g_ws2[idx] = pack2(w0, w1);
        }
        for (int idx = tid; idx < NH * 8; idx += blockDim.x) {
            int q = idx % 8, h = idx / 8;
            float bv[2];
            #pragma unroll
            for (int j = 0; j < 2; j++) {
                int och = h * CG + 2 * q + j;
                float inv = gamma[och] * rsqrtf(var[och] + 1e-5f);
                float sb = conv_b[och] + conv_b[NC + och] + conv_b[2 * NC + och];
                bv[j] = sb * inv + beta[och] - mean[och] * inv;
            }
            g_bias2[idx] = pack2(bv[0], bv[1]);
        }
    }
}

__global__ __launch_bounds__(THREADS, 3)
void blockgcn_main_kernel(const float* __restrict__ x, float* __restrict__ out)
{
    __shared__ __align__(16) float xs[CG][TB][NVP];       // 12288 B
    __shared__ __align__(16) float bnas[NK][NV][BSTRIDE]; //  9936 B

    const int tile = blockIdx.x;   // 0..31
    const int n    = blockIdx.y;   // 0..31
    const int h    = blockIdx.z;   // 0..7
    const int t0   = tile * TB;
    const int tid  = threadIdx.x;

    // ---- stage x tile (float4 LDG, scalar STS scatter) ----
    const float* xbase = x + ((size_t)(n * NC + h * CG)) * (NT * NV) + (size_t)t0 * NV;
    for (int idx = tid; idx < CG * TB * NV / 4; idx += THREADS) {  // 736 float4
        int c  = idx / (TB * NV / 4);
        int r4 = idx % (TB * NV / 4);
        float4 f = ((const float4*)(xbase + (size_t)c * (NT * NV)))[r4];
        int lin = r4 * 4;
        xs[c][lin / NV][lin % NV] = f.x;  lin++;
        xs[c][lin / NV][lin % NV] = f.y;  lin++;
        xs[c][lin / NV][lin % NV] = f.z;  lin++;
        xs[c][lin / NV][lin % NV] = f.w;
    }
    for (int idx = tid; idx < CG * TB; idx += THREADS)
        xs[idx / TB][idx % TB][NV] = 0.f;

    // ---- stage BnA ([k][w][v] rows, stride 36 floats, this h) ----
    for (int idx = tid; idx < NK * NV * NVP; idx += THREADS) {
        int k = idx / (NV * NVP), rem = idx % (NV * NVP);
        bnas[k][rem / NVP][rem % NVP] = (&g_bna[k][h][0][0])[rem];
    }
    __syncthreads();

    {
        const int t = tid / NV;
        const int w = tid % NV;

        // init: folded bias + residual, packed over o-pairs (vector bias loads)
        ull acc2[8];
        {
            const ulonglong2* bb = (const ulonglong2*)&c_bias2[h * 8];
            #pragma unroll
            for (int q = 0; q < 4; q++) {
                ulonglong2 bq = bb[q];
                acc2[2 * q]     = add2(bq.x, pack2(xs[4 * q][t][w],     xs[4 * q + 1][t][w]));
                acc2[2 * q + 1] = add2(bq.y, pack2(xs[4 * q + 2][t][w], xs[4 * q + 3][t][w]));
            }
        }

        // hoist ALL 3 BnA columns for this w (72 regs, reused for all 16 c)
        ull b0[12], b1[12], b2[12];
        {
            const ulonglong2* bp0 = (const ulonglong2*)&bnas[0][w][0];
            const ulonglong2* bp1 = (const ulonglong2*)&bnas[1][w][0];
            const ulonglong2* bp2 = (const ulonglong2*)&bnas[2][w][0];
            #pragma unroll
            for (int q = 0; q < 6; q++) {
                ulonglong2 u0 = bp0[q], u1 = bp1[q], u2 = bp2[q];
                b0[2 * q] = u0.x; b0[2 * q + 1] = u0.y;
                b1[2 * q] = u1.x; b1[2 * q + 1] = u1.y;
                b2[2 * q] = u2.x; b2[2 * q + 1] = u2.y;
            }
        }

        // per-k weight bases (constant bank), vector LDCU.128 stream
        const ulonglong2* wb0 = (const ulonglong2*)&c_ws2[(0 * NH + h) * CG * 8];
        const ulonglong2* wb1 = (const ulonglong2*)&c_ws2[(1 * NH + h) * CG * 8];
        const ulonglong2* wb2 = (const ulonglong2*)&c_ws2[(2 * NH + h) * CG * 8];

        // single pass over c: x row read ONCE, feeds all 3 k-dots
        #pragma unroll 2
        for (int c = 0; c < CG; c++) {
            const ulonglong2* xp = (const ulonglong2*)&xs[c][t][0];
            ull s0 = 0ull, s1 = 0ull, s2 = 0ull;
            #pragma unroll
            for (int q = 0; q < 6; q++) {
                ulonglong2 u = xp[q];          // consumed immediately
                s0 = fma2(u.x, b0[2 * q],     s0);
                s1 = fma2(u.x, b1[2 * q],     s1);
                s2 = fma2(u.x, b2[2 * q],     s2);
                s0 = fma2(u.y, b0[2 * q + 1], s0);
                s1 = fma2(u.y, b1[2 * q + 1], s1);
                s2 = fma2(u.y, b2[2 * q + 1], s2);
            }
            float f0 = hsum2(s0), f1 = hsum2(s1), f2 = hsum2(s2);
            ull sp0 = pack2(f0, f0);
            ull sp1 = pack2(f1, f1);
            ull sp2 = pack2(f2, f2);
            #pragma unroll
            for (int q = 0; q < 4; q++) {
                ulonglong2 w0 = wb0[c * 4 + q];     // LDCU.128
                ulonglong2 w1 = wb1[c * 4 + q];
                ulonglong2 w2 = wb2[c * 4 + q];
                acc2[2 * q] = fma2(sp2, w2.x,
                              fma2(sp1, w1.x,
                              fma2(sp0, w0.x, acc2[2 * q])));
                acc2[2 * q + 1] = fma2(sp2, w2.y,
                                  fma2(sp1, w1.y,
                                  fma2(sp0, w0.y, acc2[2 * q + 1])));
            }
        }

        // epilogue: relu + store
        float* ob = out + ((size_t)(n * NC + h * CG)) * (NT * NV)
                        + (size_t)(t0 + t) * NV + w;
        #pragma unroll
        for (int q = 0; q < 8; q++) {
            float a, b;
            unpack2(acc2[q], a, b);
            ob[(size_t)(2 * q)     * (NT * NV)] = fmaxf(a, 0.f);
            ob[(size_t)(2 * q + 1) * (NT * NV)] = fmaxf(b, 0.f);
        }
    }
}

extern "C" void kernel_launch(void* const* d_in, const int* in_sizes, int n_in,
                              void* d_out, int out_size)
{
    const float* x      = (const float*)d_in[0];
    const float* emb    = (const float*)d_in[1];
    const float* A      = (const float*)d_in[2];
    const float* conv_w = (const float*)d_in[3];
    const float* conv_b = (const float*)d_in[4];
    const float* gamma  = (const float*)d_in[5];
    const float* beta   = (const float*)d_in[6];
    const float* mean   = (const float*)d_in[7];
    const float* var    = (const float*)d_in[8];
    const int*   hop    = (const int*)d_in[9];

    int n_hop = in_sizes[1] / (NK * NH);

    precompute_kernel<<<NK * NH + 1, 256>>>(emb, A, conv_w, conv_b,
                                            gamma, beta, mean, var, hop, n_hop);

    void* ws2_src = nullptr;
    void* bias2_src = nullptr;
    cudaGetSymbolAddress(&ws2_src, g_ws2);
    cudaGetSymbolAddress(&bias2_src, g_bias2);
    cudaMemcpyToSymbolAsync(c_ws2, ws2_src, sizeof(ull) * NK * NH * CG * 8, 0,
                            cudaMemcpyDeviceToDevice, 0);
    cudaMemcpyToSymbolAsync(c_bias2, bias2_src, sizeof(ull) * NH * 8, 0,
                            cudaMemcpyDeviceToDevice, 0);

    dim3 grid(NT / TB, NN, NH);
    blockgcn_main_kernel<<<grid, THREADS>>>(x, (float*)d_out);
}